// round 2
// baseline (speedup 1.0000x reference)
#include <cuda_runtime.h>
#include <cuda_bf16.h>

// Problem constants (fixed by the reference).
static constexpr int Bn = 128;   // batch
static constexpr int Qn = 1000;  // queries
static constexpr int Cn = 256;   // classes
static constexpr int Tn = 300;   // targets
static constexpr int WARPS = 8;  // q-rows per block
static constexpr int NTHREADS = WARPS * 32;

// If labels were materialized as int64 (little-endian), every odd 32-bit word
// of the buffer is zero (labels in [0,256)). Probe 16 odd words.
__device__ __forceinline__ bool labels_are_i64(const int* __restrict__ p) {
    int acc = 0;
#pragma unroll
    for (int i = 0; i < 16; i++) acc |= p[2 * i + 1];
    return acc == 0;
}

__global__ __launch_bounds__(NTHREADS)
void hungarian_cost_kernel(const float* __restrict__ logits,
                           const float* __restrict__ pboxes,
                           const int*   __restrict__ labels_raw,
                           const float* __restrict__ tboxes,
                           float*       __restrict__ out) {
    __shared__ float4 s_tb[Tn];            // tgt boxes for this batch  (4.8 KB)
    __shared__ int    s_lab[Tn];           // labels                    (1.2 KB)
    __shared__ float  s_prob[WARPS][Cn];   // -softmax per q-row        (8 KB)

    const int b   = blockIdx.y;
    const int q0  = blockIdx.x * WARPS;
    const int tid = threadIdx.x;
    const int w   = tid >> 5;
    const int l   = tid & 31;
    const int q   = q0 + w;

    const bool is64 = labels_are_i64(labels_raw);

    // Stage target boxes + labels for batch b into smem (block-cooperative).
    {
        float* tbf = reinterpret_cast<float*>(s_tb);
        const float* src = tboxes + b * Tn * 4;
        for (int i = tid; i < Tn * 4; i += NTHREADS) tbf[i] = src[i];
        for (int i = tid; i < Tn; i += NTHREADS) {
            int idx = b * Tn + i;
            s_lab[i] = is64 ? labels_raw[2 * idx] : labels_raw[idx];
        }
    }

    // ---- Softmax over 256 classes for this warp's q-row (warp-local). ----
    const float* lg = logits + ((b * Qn) + q) * Cn;
    float v[8];
    float mx = -1e30f;
#pragma unroll
    for (int i = 0; i < 8; i++) {
        v[i] = lg[i * 32 + l];
        mx = fmaxf(mx, v[i]);
    }
#pragma unroll
    for (int o = 16; o; o >>= 1) mx = fmaxf(mx, __shfl_xor_sync(0xffffffffu, mx, o));
    float s = 0.0f;
#pragma unroll
    for (int i = 0; i < 8; i++) {
        v[i] = __expf(v[i] - mx);
        s += v[i];
    }
#pragma unroll
    for (int o = 16; o; o >>= 1) s += __shfl_xor_sync(0xffffffffu, s, o);
    const float ninv = -1.0f / s;
#pragma unroll
    for (int i = 0; i < 8; i++) s_prob[w][i * 32 + l] = v[i] * ninv;

    // Pred box for this q-row (same 16B load in all lanes -> L1 broadcast).
    const float4 pb = *reinterpret_cast<const float4*>(pboxes + ((b * Qn) + q) * 4);

    __syncthreads();  // s_tb / s_lab ready (s_prob is warp-private)

    // ---- Emit 300 outputs for this q-row, coalesced. ----
    float* orow = out + ((b * Qn) + q) * Tn;
    const float* pw = s_prob[w];
#pragma unroll 2
    for (int t = l; t < Tn; t += 32) {
        const float4 tb = s_tb[t];
        float cb = fabsf(pb.x - tb.x) + fabsf(pb.y - tb.y) +
                   fabsf(pb.z - tb.z) + fabsf(pb.w - tb.w);
        orow[t] = cb + pw[s_lab[t]];
    }
}

extern "C" void kernel_launch(void* const* d_in, const int* in_sizes, int n_in,
                              void* d_out, int out_size) {
    const float* logits = (const float*)d_in[0];
    const float* pboxes = (const float*)d_in[1];
    const int*   labels = (const int*)d_in[2];
    const float* tboxes = (const float*)d_in[3];
    float* out = (float*)d_out;

    dim3 grid(Qn / WARPS, Bn);  // 125 x 128
    hungarian_cost_kernel<<<grid, NTHREADS>>>(logits, pboxes, labels, tboxes, out);
}

// round 3
// speedup vs baseline: 1.0149x; 1.0149x over previous
#include <cuda_runtime.h>
#include <cuda_bf16.h>

// Problem constants (fixed by the reference).
static constexpr int Bn = 128;   // batch
static constexpr int Qn = 1000;  // queries
static constexpr int Cn = 256;   // classes
static constexpr int Tn = 300;   // targets
static constexpr int WARPS = 8;  // q-rows per block
static constexpr int NTHREADS = WARPS * 32;

// If labels were materialized as int64 (little-endian), every odd 32-bit word
// of the buffer is zero (labels in [0,256)). Probe 16 odd words.
__device__ __forceinline__ bool labels_are_i64(const int* __restrict__ p) {
    int acc = 0;
#pragma unroll
    for (int i = 0; i < 16; i++) acc |= p[2 * i + 1];
    return acc == 0;
}

__global__ __launch_bounds__(NTHREADS)
void hungarian_cost_kernel(const float* __restrict__ logits,
                           const float* __restrict__ pboxes,
                           const int*   __restrict__ labels_raw,
                           const float* __restrict__ tboxes,
                           float*       __restrict__ out) {
    __shared__ float4 s_tb[Tn];            // tgt boxes for this batch  (4.8 KB)
    __shared__ int    s_lab[Tn];           // labels                    (1.2 KB)
    __shared__ float  s_prob[WARPS][Cn];   // -softmax per q-row        (8 KB)

    const int b   = blockIdx.y;
    const int q0  = blockIdx.x * WARPS;
    const int tid = threadIdx.x;
    const int w   = tid >> 5;
    const int l   = tid & 31;
    const int q   = q0 + w;

    const bool is64 = labels_are_i64(labels_raw);

    // Stage target boxes + labels for batch b into smem (block-cooperative).
    {
        float* tbf = reinterpret_cast<float*>(s_tb);
        const float* src = tboxes + b * Tn * 4;
        for (int i = tid; i < Tn * 4; i += NTHREADS) tbf[i] = src[i];
        for (int i = tid; i < Tn; i += NTHREADS) {
            int idx = b * Tn + i;
            s_lab[i] = is64 ? labels_raw[2 * idx] : labels_raw[idx];
        }
    }

    // ---- Softmax over 256 classes for this warp's q-row (warp-local). ----
    const float* lg = logits + ((b * Qn) + q) * Cn;
    float v[8];
    float mx = -1e30f;
#pragma unroll
    for (int i = 0; i < 8; i++) {
        v[i] = lg[i * 32 + l];
        mx = fmaxf(mx, v[i]);
    }
#pragma unroll
    for (int o = 16; o; o >>= 1) mx = fmaxf(mx, __shfl_xor_sync(0xffffffffu, mx, o));
    float s = 0.0f;
#pragma unroll
    for (int i = 0; i < 8; i++) {
        v[i] = __expf(v[i] - mx);
        s += v[i];
    }
#pragma unroll
    for (int o = 16; o; o >>= 1) s += __shfl_xor_sync(0xffffffffu, s, o);
    const float ninv = -1.0f / s;
#pragma unroll
    for (int i = 0; i < 8; i++) s_prob[w][i * 32 + l] = v[i] * ninv;

    // Pred box for this q-row (same 16B load in all lanes -> L1 broadcast).
    const float4 pb = *reinterpret_cast<const float4*>(pboxes + ((b * Qn) + q) * 4);

    __syncthreads();  // s_tb / s_lab ready (s_prob is warp-private)

    // ---- Emit 300 outputs for this q-row, coalesced. ----
    float* orow = out + ((b * Qn) + q) * Tn;
    const float* pw = s_prob[w];
#pragma unroll 2
    for (int t = l; t < Tn; t += 32) {
        const float4 tb = s_tb[t];
        float cb = fabsf(pb.x - tb.x) + fabsf(pb.y - tb.y) +
                   fabsf(pb.z - tb.z) + fabsf(pb.w - tb.w);
        orow[t] = cb + pw[s_lab[t]];
    }
}

extern "C" void kernel_launch(void* const* d_in, const int* in_sizes, int n_in,
                              void* d_out, int out_size) {
    const float* logits = (const float*)d_in[0];
    const float* pboxes = (const float*)d_in[1];
    const int*   labels = (const int*)d_in[2];
    const float* tboxes = (const float*)d_in[3];
    float* out = (float*)d_out;

    dim3 grid(Qn / WARPS, Bn);  // 125 x 128
    hungarian_cost_kernel<<<grid, NTHREADS>>>(logits, pboxes, labels, tboxes, out);
}